// round 10
// baseline (speedup 1.0000x reference)
#include <cuda_runtime.h>
#include <cuda_fp16.h>
#include <cstdint>
#include <math.h>

#define BS   32768
#define NQ   8
#define FFN  2048
#define EMB  512

#define TMT  128
#define TNT  128
#define KC   64
#define NC   (FFN / KC)       // 32
#define NTH  128
#define ROWB 144

__device__ __half g_h[BS * FFN];
__device__ __half g_w2t[EMB * FFN];

// ---- smem: 2 stages x (A 128x144 + B 128x144) = 72 KB ----
#define SM_A(s)  ((s) * 36864)
#define SM_B(s)  ((s) * 36864 + 18432)
#define SMEM_BYTES 73728

__device__ __forceinline__ uint32_t smem_u32(const void* p) {
    uint32_t a;
    asm("{ .reg .u64 t; cvta.to.shared.u64 t, %1; cvt.u32.u64 %0, t; }" : "=r"(a) : "l"(p));
    return a;
}

#define LDSM4(r, a)                                                            \
    asm volatile("ldmatrix.sync.aligned.m8n8.x4.shared.b16 {%0,%1,%2,%3}, [%4];" \
        : "=r"((r)[0]), "=r"((r)[1]), "=r"((r)[2]), "=r"((r)[3]) : "r"(a))

#define MMAF16(d, a, b0, b1v)                                                  \
    asm volatile("mma.sync.aligned.m16n8k16.row.col.f32.f16.f16.f32 "         \
        "{%0,%1,%2,%3},{%4,%5,%6,%7},{%8,%9},{%0,%1,%2,%3};"                  \
        : "+f"((d)[0]), "+f"((d)[1]), "+f"((d)[2]), "+f"((d)[3])              \
        : "r"((a)[0]), "r"((a)[1]), "r"((a)[2]), "r"((a)[3]), "r"(b0), "r"(b1v))

// f16-accumulator variants: D/C are 2 b32 regs (4 packed halves)
#define MMAH16_Z(d, a, b0, b1v)                                                \
    asm volatile("mma.sync.aligned.m16n8k16.row.col.f16.f16.f16.f16 "         \
        "{%0,%1},{%2,%3,%4,%5},{%6,%7},{%8,%8};"                              \
        : "=r"((d)[0]), "=r"((d)[1])                                          \
        : "r"((a)[0]), "r"((a)[1]), "r"((a)[2]), "r"((a)[3]),                 \
          "r"(b0), "r"(b1v), "r"(0u))

#define MMAH16(d, a, b0, b1v)                                                  \
    asm volatile("mma.sync.aligned.m16n8k16.row.col.f16.f16.f16.f16 "         \
        "{%0,%1},{%2,%3,%4,%5},{%6,%7},{%0,%1};"                              \
        : "+r"((d)[0]), "+r"((d)[1])                                          \
        : "r"((a)[0]), "r"((a)[1]), "r"((a)[2]), "r"((a)[3]), "r"(b0), "r"(b1v))

#define CP16(dst, src)                                                         \
    asm volatile("cp.async.cg.shared.global [%0], [%1], 16;" :: "r"(dst), "l"(src))
#define CP_COMMIT() asm volatile("cp.async.commit_group;" ::: "memory")
#define CP_WAIT1()  asm volatile("cp.async.wait_group 1;" ::: "memory")

// ---- prep: W2 [FFN][EMB] fp32 -> fp16 transposed [EMB][FFN] ----------------
__global__ void prep_w2_kernel(const float* __restrict__ W2) {
    int t = blockIdx.x * blockDim.x + threadIdx.x;
    if (t >= EMB * FFN) return;
    int n = t >> 11;
    int k = t & (FFN - 1);
    g_w2t[t] = __float2half_rn(W2[(size_t)k * EMB + n]);
}

// ---- kernel 1: H = fp16(relu(q @ W1 + b1)) ---------------------------------
#define TB 64
__global__ __launch_bounds__(256, 2)
void h_kernel(const float* __restrict__ x,
              const float* __restrict__ theta,
              const float* __restrict__ W1,
              const float* __restrict__ b1)
{
    __shared__ float q_s[TB][NQ];
    const int tid  = threadIdx.x;
    const int row0 = blockIdx.x * TB;
    const int k0   = tid * 8;

    #pragma unroll
    for (int i = tid; i < TB * NQ; i += 256) {
        int m = i >> 3, j = i & 7;
        q_s[m][j] = cosf(x[(size_t)(row0 + m) * NQ + j]) * cosf(__ldg(&theta[j]));
    }

    float w1r[8][NQ];
    float b1r[8];
    #pragma unroll
    for (int u = 0; u < 8; u++) {
        b1r[u] = __ldg(&b1[k0 + u]);
        #pragma unroll
        for (int j = 0; j < NQ; j++)
            w1r[u][j] = __ldg(&W1[(size_t)j * FFN + k0 + u]);
    }
    __syncthreads();

    for (int t = 0; t < TB; t++) {
        float4 qa = *(const float4*)&q_s[t][0];
        float4 qb = *(const float4*)&q_s[t][4];
        uint32_t w[4];
        #pragma unroll
        for (int u = 0; u < 8; u++) {
            float s = b1r[u];
            s = fmaf(qa.x, w1r[u][0], s); s = fmaf(qa.y, w1r[u][1], s);
            s = fmaf(qa.z, w1r[u][2], s); s = fmaf(qa.w, w1r[u][3], s);
            s = fmaf(qb.x, w1r[u][4], s); s = fmaf(qb.y, w1r[u][5], s);
            s = fmaf(qb.z, w1r[u][6], s); s = fmaf(qb.w, w1r[u][7], s);
            s = fmaxf(s, 0.f);
            uint32_t hb = (uint32_t)__half_as_ushort(__float2half_rn(s));
            if (u & 1) w[u >> 1] |= hb << 16;
            else       w[u >> 1]  = hb;
        }
        *(uint4*)((char*)(g_h + (size_t)(row0 + t) * FFN) + tid * 16)
            = make_uint4(w[0], w[1], w[2], w[3]);
    }
}

// ============ shared GEMM scaffolding (identical to R8 best) =================
struct GemmCtx {
    uint32_t smb, a_off, b_off, soA;
    const char *gA, *gB;
    int row0, col0, wm, wn, lane;
};

__device__ __forceinline__ GemmCtx gemm_setup(char* sm, int row_base) {
    GemmCtx c;
    c.smb = smem_u32(sm);
    const int tid  = threadIdx.x;
    const int wid  = tid >> 5;
    c.lane = tid & 31;
    c.col0 = blockIdx.x * TNT;
    c.row0 = row_base + blockIdx.y * TMT;
    c.wm   = wid & 1;
    c.wn   = wid >> 1;
    c.a_off = (uint32_t)(c.wm * 64 + (c.lane & 15)) * ROWB + ((c.lane >> 4) << 4);
    c.b_off = (uint32_t)(c.wn * 64 + (c.lane & 7) + ((c.lane & 16) >> 1)) * ROWB
            + ((c.lane & 8) << 1);
    const int ldr = tid >> 3;
    const int seg = (tid & 7) * 16;
    c.gA  = (const char*)(g_h   + (size_t)(c.row0 + ldr) * FFN) + seg;
    c.gB  = (const char*)(g_w2t + (size_t)(c.col0 + ldr) * FFN) + seg;
    c.soA = (uint32_t)ldr * ROWB + seg;
    return c;
}

__device__ __forceinline__ void gemm_issue(const GemmCtx& c, int chunk, int s) {
    const char* a = c.gA + chunk * (KC * 2);
    const char* b = c.gB + chunk * (KC * 2);
    #pragma unroll
    for (int r = 0; r < 8; r++) {
        CP16(c.smb + SM_A(s) + c.soA + r * 16 * ROWB, a + (size_t)r * 16 * FFN * 2);
        CP16(c.smb + SM_B(s) + c.soA + r * 16 * ROWB, b + (size_t)r * 16 * FFN * 2);
    }
}

__device__ __forceinline__ void gemm_epilogue(const GemmCtx& c, float acc[4][8][4],
                                              const float* b2, float* out) {
    #pragma unroll
    for (int mt = 0; mt < 4; mt++) {
        int mrow = c.row0 + c.wm * 64 + mt * 16 + (c.lane >> 2);
        #pragma unroll
        for (int nt = 0; nt < 8; nt++) {
            int ncol = c.col0 + c.wn * 64 + nt * 8 + (c.lane & 3) * 2;
            float bx = b2[ncol], by = b2[ncol + 1];
            float2 v0 = make_float2(acc[mt][nt][0] + bx, acc[mt][nt][1] + by);
            float2 v1 = make_float2(acc[mt][nt][2] + bx, acc[mt][nt][3] + by);
            *(float2*)&out[(size_t)mrow * EMB + ncol]       = v0;
            *(float2*)&out[(size_t)(mrow + 8) * EMB + ncol] = v1;
        }
    }
}

// ---- A: fp32-accumulator GEMM (R8-exact), rows [0, BS/2) -------------------
__global__ __launch_bounds__(NTH, 2)
void gemm_f32acc(const float* __restrict__ b2, float* __restrict__ out)
{
    extern __shared__ char sm[];
    GemmCtx c = gemm_setup(sm, 0);

    float acc[4][8][4];
    #pragma unroll
    for (int a = 0; a < 4; a++)
        #pragma unroll
        for (int b = 0; b < 8; b++)
            #pragma unroll
            for (int i = 0; i < 4; i++) acc[a][b][i] = 0.f;

    gemm_issue(c, 0, 0);
    CP_COMMIT();

    for (int ch = 0; ch < NC; ch++) {
        const int s = ch & 1;
        if (ch + 1 < NC) gemm_issue(c, ch + 1, s ^ 1);
        CP_COMMIT();
        CP_WAIT1();
        __syncthreads();

        const uint32_t A = c.smb + SM_A(s) + c.a_off;
        const uint32_t B = c.smb + SM_B(s) + c.b_off;
        #pragma unroll
        for (int ks = 0; ks < 4; ks++) {
            uint32_t ah[4][4];
            #pragma unroll
            for (int mt = 0; mt < 4; mt++)
                LDSM4(ah[mt], A + mt * 16 * ROWB + ks * 32);
            #pragma unroll
            for (int g = 0; g < 4; g++) {
                uint32_t bh[4];
                LDSM4(bh, B + g * 16 * ROWB + ks * 32);
                #pragma unroll
                for (int mt = 0; mt < 4; mt++) {
                    MMAF16(acc[mt][2 * g],     ah[mt], bh[0], bh[1]);
                    MMAF16(acc[mt][2 * g + 1], ah[mt], bh[2], bh[3]);
                }
            }
        }
        __syncthreads();
    }
    gemm_epilogue(c, acc, b2, out);
}

// ---- B: fp16-accumulator GEMM + K32 fp32 promotion, rows [BS/2, BS) --------
__global__ __launch_bounds__(NTH, 2)
void gemm_f16acc(const float* __restrict__ b2, float* __restrict__ out)
{
    extern __shared__ char sm[];
    GemmCtx c = gemm_setup(sm, BS / 2);

    float acc[4][8][4];
    #pragma unroll
    for (int a = 0; a < 4; a++)
        #pragma unroll
        for (int b = 0; b < 8; b++)
            #pragma unroll
            for (int i = 0; i < 4; i++) acc[a][b][i] = 0.f;

    gemm_issue(c, 0, 0);
    CP_COMMIT();

    for (int ch = 0; ch < NC; ch++) {
        const int s = ch & 1;
        if (ch + 1 < NC) gemm_issue(c, ch + 1, s ^ 1);
        CP_COMMIT();
        CP_WAIT1();
        __syncthreads();

        const uint32_t A = c.smb + SM_A(s) + c.a_off;
        const uint32_t B = c.smb + SM_B(s) + c.b_off;
        uint32_t acch[4][8][2];               // f16x2 micro-accumulators

        #pragma unroll
        for (int grp = 0; grp < 2; grp++) {   // each group = K32 in f16
            #pragma unroll
            for (int k2 = 0; k2 < 2; k2++) {
                const int ks = grp * 2 + k2;
                uint32_t ah[4][4];
                #pragma unroll
                for (int mt = 0; mt < 4; mt++)
                    LDSM4(ah[mt], A + mt * 16 * ROWB + ks * 32);
                #pragma unroll
                for (int g = 0; g < 4; g++) {
                    uint32_t bh[4];
                    LDSM4(bh, B + g * 16 * ROWB + ks * 32);
                    #pragma unroll
                    for (int mt = 0; mt < 4; mt++) {
                        if (k2 == 0) {
                            MMAH16_Z(acch[mt][2 * g],     ah[mt], bh[0], bh[1]);
                            MMAH16_Z(acch[mt][2 * g + 1], ah[mt], bh[2], bh[3]);
                        } else {
                            MMAH16(acch[mt][2 * g],     ah[mt], bh[0], bh[1]);
                            MMAH16(acch[mt][2 * g + 1], ah[mt], bh[2], bh[3]);
                        }
                    }
                }
            }
            // promote f16 micro-accumulators into fp32
            #pragma unroll
            for (int mt = 0; mt < 4; mt++)
                #pragma unroll
                for (int nt = 0; nt < 8; nt++) {
                    float2 lo = __half22float2(*(__half2*)&acch[mt][nt][0]);
                    float2 hi = __half22float2(*(__half2*)&acch[mt][nt][1]);
                    acc[mt][nt][0] += lo.x; acc[mt][nt][1] += lo.y;
                    acc[mt][nt][2] += hi.x; acc[mt][nt][3] += hi.y;
                }
        }
        __syncthreads();
    }
    gemm_epilogue(c, acc, b2, out);
}

// ---- launcher ----------------------------------------------------------------
extern "C" void kernel_launch(void* const* d_in, const int* in_sizes, int n_in,
                              void* d_out, int out_size)
{
    const float *x = 0, *theta = 0, *W1 = 0, *b1 = 0, *W2 = 0, *b2 = 0;
    for (int i = 0; i < n_in; i++) {
        switch (in_sizes[i]) {
            case BS * NQ:   x     = (const float*)d_in[i]; break;
            case NQ:        theta = (const float*)d_in[i]; break;
            case NQ * FFN:  W1    = (const float*)d_in[i]; break;
            case FFN:       b1    = (const float*)d_in[i]; break;
            case FFN * EMB: W2    = (const float*)d_in[i]; break;
            case EMB:       b2    = (const float*)d_in[i]; break;
            default: break;
        }
    }

    prep_w2_kernel<<<(EMB * FFN + 255) / 256, 256>>>(W2);
    h_kernel<<<BS / TB, 256>>>(x, theta, W1, b1);

    cudaFuncSetAttribute(gemm_f32acc, cudaFuncAttributeMaxDynamicSharedMemorySize,
                         SMEM_BYTES);
    cudaFuncSetAttribute(gemm_f16acc, cudaFuncAttributeMaxDynamicSharedMemorySize,
                         SMEM_BYTES);

    dim3 grid(EMB / TNT, (BS / 2) / TMT);   // 4 x 128 each
    gemm_f32acc<<<grid, NTH, SMEM_BYTES>>>(b2, (float*)d_out);
    gemm_f16acc<<<grid, NTH, SMEM_BYTES>>>(b2, (float*)d_out);
}

// round 11
// speedup vs baseline: 1.3568x; 1.3568x over previous
#include <cuda_runtime.h>
#include <cuda_fp16.h>
#include <cstdint>
#include <math.h>

#define BS   32768
#define NQ   8
#define FFN  2048
#define EMB  512

#define TMT  128              // tokens per CTA (GEMM)
#define TNT  64               // out cols per CTA
#define KC   64               // FFN chunk per iteration
#define NC   (FFN / KC)       // 32
#define NTH  128              // 4 warps: 2x2 grid of 64x32 warp tiles
#define ROWB 144              // 128B data + 16B pad -> ldmatrix conflict-free

__device__ __half g_h[BS * FFN];
__device__ __half g_w2t[EMB * FFN];

// ---- smem: 2 stages x (A 128x144 + B 64x144) = 54 KB -> 4 CTAs/SM ----
#define SM_A(s)  ((s) * 27648)
#define SM_B(s)  ((s) * 27648 + 18432)
#define SMEM_BYTES 55296

__device__ __forceinline__ uint32_t smem_u32(const void* p) {
    uint32_t a;
    asm("{ .reg .u64 t; cvta.to.shared.u64 t, %1; cvt.u32.u64 %0, t; }" : "=r"(a) : "l"(p));
    return a;
}

#define LDSM4(r, a)                                                            \
    asm volatile("ldmatrix.sync.aligned.m8n8.x4.shared.b16 {%0,%1,%2,%3}, [%4];" \
        : "=r"((r)[0]), "=r"((r)[1]), "=r"((r)[2]), "=r"((r)[3]) : "r"(a))

#define MMAF16(d, a, b0, b1v)                                                  \
    asm volatile("mma.sync.aligned.m16n8k16.row.col.f32.f16.f16.f32 "         \
        "{%0,%1,%2,%3},{%4,%5,%6,%7},{%8,%9},{%0,%1,%2,%3};"                  \
        : "+f"((d)[0]), "+f"((d)[1]), "+f"((d)[2]), "+f"((d)[3])              \
        : "r"((a)[0]), "r"((a)[1]), "r"((a)[2]), "r"((a)[3]), "r"(b0), "r"(b1v))

#define CP16(dst, src)                                                         \
    asm volatile("cp.async.cg.shared.global [%0], [%1], 16;" :: "r"(dst), "l"(src))
#define CP_COMMIT() asm volatile("cp.async.commit_group;" ::: "memory")
#define CP_WAIT1()  asm volatile("cp.async.wait_group 1;" ::: "memory")

// ---- prep: W2 [FFN][EMB] fp32 -> fp16 transposed [EMB][FFN] ----------------
__global__ void prep_w2_kernel(const float* __restrict__ W2) {
    int t = blockIdx.x * blockDim.x + threadIdx.x;
    if (t >= EMB * FFN) return;
    int n = t >> 11;
    int k = t & (FFN - 1);
    g_w2t[t] = __float2half_rn(W2[(size_t)k * EMB + n]);
}

// ---- kernel 1: H = fp16(relu(q @ W1 + b1)) (R8-exact) ----------------------
#define TB 64
__global__ __launch_bounds__(256, 2)
void h_kernel(const float* __restrict__ x,
              const float* __restrict__ theta,
              const float* __restrict__ W1,
              const float* __restrict__ b1)
{
    __shared__ float q_s[TB][NQ];
    const int tid  = threadIdx.x;
    const int row0 = blockIdx.x * TB;
    const int k0   = tid * 8;

    #pragma unroll
    for (int i = tid; i < TB * NQ; i += 256) {
        int m = i >> 3, j = i & 7;
        q_s[m][j] = cosf(x[(size_t)(row0 + m) * NQ + j]) * cosf(__ldg(&theta[j]));
    }

    float w1r[8][NQ];
    float b1r[8];
    #pragma unroll
    for (int u = 0; u < 8; u++) {
        b1r[u] = __ldg(&b1[k0 + u]);
        #pragma unroll
        for (int j = 0; j < NQ; j++)
            w1r[u][j] = __ldg(&W1[(size_t)j * FFN + k0 + u]);
    }
    __syncthreads();

    for (int t = 0; t < TB; t++) {
        float4 qa = *(const float4*)&q_s[t][0];
        float4 qb = *(const float4*)&q_s[t][4];
        uint32_t w[4];
        #pragma unroll
        for (int u = 0; u < 8; u++) {
            float s = b1r[u];
            s = fmaf(qa.x, w1r[u][0], s); s = fmaf(qa.y, w1r[u][1], s);
            s = fmaf(qa.z, w1r[u][2], s); s = fmaf(qa.w, w1r[u][3], s);
            s = fmaf(qb.x, w1r[u][4], s); s = fmaf(qb.y, w1r[u][5], s);
            s = fmaf(qb.z, w1r[u][6], s); s = fmaf(qb.w, w1r[u][7], s);
            s = fmaxf(s, 0.f);
            uint32_t hb = (uint32_t)__half_as_ushort(__float2half_rn(s));
            if (u & 1) w[u >> 1] |= hb << 16;
            else       w[u >> 1]  = hb;
        }
        *(uint4*)((char*)(g_h + (size_t)(row0 + t) * FFN) + tid * 16)
            = make_uint4(w[0], w[1], w[2], w[3]);
    }
}

// ---- gemm: out = H @ W2 + b2; 128x64 CTA, 4 CTAs/SM ------------------------
__global__ __launch_bounds__(NTH, 4)
void gemm_kernel(const float* __restrict__ b2, float* __restrict__ out)
{
    extern __shared__ char sm[];
    const uint32_t smb = smem_u32(sm);

    const int tid  = threadIdx.x;
    const int wid  = tid >> 5;
    const int lane = tid & 31;
    const int col0 = blockIdx.x * TNT;      // x fastest: 8 col CTAs share A via L2
    const int row0 = blockIdx.y * TMT;
    const int wm   = wid & 1;               // 2 M groups of 64 rows
    const int wn   = wid >> 1;              // 2 N groups of 32 cols

    const uint32_t a_off = (uint32_t)(wm * 64 + (lane & 15)) * ROWB + ((lane >> 4) << 4);
    const uint32_t b_off = (uint32_t)(wn * 32 + (lane & 7) + ((lane & 16) >> 1)) * ROWB
                         + ((lane & 8) << 1);

    // cp.async: thread covers row = (tid>>3) + 16*r, 16B segment = tid&7
    const int ldr = tid >> 3;
    const int seg = (tid & 7) * 16;
    const char* gA = (const char*)(g_h   + (size_t)(row0 + ldr) * FFN) + seg;
    const char* gB = (const char*)(g_w2t + (size_t)(col0 + ldr) * FFN) + seg;
    const uint32_t soA = (uint32_t)ldr * ROWB + seg;

    auto issue = [&](int chunk, int s) {
        const char* a = gA + chunk * (KC * 2);
        const char* b = gB + chunk * (KC * 2);
        #pragma unroll
        for (int r = 0; r < 8; r++)         // A: 128 rows
            CP16(smb + SM_A(s) + soA + r * 16 * ROWB, a + (size_t)r * 16 * FFN * 2);
        #pragma unroll
        for (int r = 0; r < 4; r++)         // B: 64 rows
            CP16(smb + SM_B(s) + soA + r * 16 * ROWB, b + (size_t)r * 16 * FFN * 2);
    };

    float acc[4][4][4];
    #pragma unroll
    for (int a = 0; a < 4; a++)
        #pragma unroll
        for (int b = 0; b < 4; b++)
            #pragma unroll
            for (int i = 0; i < 4; i++) acc[a][b][i] = 0.f;

    issue(0, 0);
    CP_COMMIT();

    for (int c = 0; c < NC; c++) {
        const int s = c & 1;

        if (c + 1 < NC) issue(c + 1, s ^ 1);
        CP_COMMIT();
        CP_WAIT1();             // chunk c landed; c+1 may stay in flight
        __syncthreads();

        const uint32_t A = smb + SM_A(s) + a_off;
        const uint32_t B = smb + SM_B(s) + b_off;
        #pragma unroll
        for (int ks = 0; ks < 4; ks++) {
            uint32_t ah[4][4];
            #pragma unroll
            for (int mt = 0; mt < 4; mt++)
                LDSM4(ah[mt], A + mt * 16 * ROWB + ks * 32);
            #pragma unroll
            for (int g = 0; g < 2; g++) {
                uint32_t bh[4];
                LDSM4(bh, B + g * 16 * ROWB + ks * 32);
                #pragma unroll
                for (int mt = 0; mt < 4; mt++) {
                    MMAF16(acc[mt][2 * g],     ah[mt], bh[0], bh[1]);
                    MMAF16(acc[mt][2 * g + 1], ah[mt], bh[2], bh[3]);
                }
            }
        }
        __syncthreads();        // stage s free for prefetch next iter
    }

    // epilogue: D frags + b2
    #pragma unroll
    for (int mt = 0; mt < 4; mt++) {
        int mrow = row0 + wm * 64 + mt * 16 + (lane >> 2);
        #pragma unroll
        for (int nt = 0; nt < 4; nt++) {
            int ncol = col0 + wn * 32 + nt * 8 + (lane & 3) * 2;
            float bx = b2[ncol], by = b2[ncol + 1];
            float2 v0 = make_float2(acc[mt][nt][0] + bx, acc[mt][nt][1] + by);
            float2 v1 = make_float2(acc[mt][nt][2] + bx, acc[mt][nt][3] + by);
            *(float2*)&out[(size_t)mrow * EMB + ncol]       = v0;
            *(float2*)&out[(size_t)(mrow + 8) * EMB + ncol] = v1;
        }
    }
}

// ---- launcher ----------------------------------------------------------------
extern "C" void kernel_launch(void* const* d_in, const int* in_sizes, int n_in,
                              void* d_out, int out_size)
{
    const float *x = 0, *theta = 0, *W1 = 0, *b1 = 0, *W2 = 0, *b2 = 0;
    for (int i = 0; i < n_in; i++) {
        switch (in_sizes[i]) {
            case BS * NQ:   x     = (const float*)d_in[i]; break;
            case NQ:        theta = (const float*)d_in[i]; break;
            case NQ * FFN:  W1    = (const float*)d_in[i]; break;
            case FFN:       b1    = (const float*)d_in[i]; break;
            case FFN * EMB: W2    = (const float*)d_in[i]; break;
            case EMB:       b2    = (const float*)d_in[i]; break;
            default: break;
        }
    }

    prep_w2_kernel<<<(EMB * FFN + 255) / 256, 256>>>(W2);
    h_kernel<<<BS / TB, 256>>>(x, theta, W1, b1);

    cudaFuncSetAttribute(gemm_kernel, cudaFuncAttributeMaxDynamicSharedMemorySize,
                         SMEM_BYTES);
    dim3 grid(EMB / TNT, BS / TMT);   // 8 x 256; col-fastest for L2 A reuse
    gemm_kernel<<<grid, NTH, SMEM_BYTES>>>(b2, (float*)d_out);
}